// round 9
// baseline (speedup 1.0000x reference)
#include <cuda_runtime.h>

#define HIDDEN 32
#define FEAT 30
#define NK 29                 /* feature 29 (mask bit) folded into bias */
#define TSTEPS 512
#define BATCH 4096
#define NS 4
#define CHUNK 8
#define TSF (TSTEPS * FEAT)

typedef unsigned long long ull;

__device__ __forceinline__ float tanhap(float x) {
    float y; asm("tanh.approx.f32 %0, %1;" : "=f"(y) : "f"(x)); return y;
}
__device__ __forceinline__ float sigf(float x) {
    return fmaf(0.5f, tanhap(0.5f * x), 0.5f);
}
__device__ __forceinline__ ull fma2(ull a, ull b, ull c) {
    ull d;
    asm("fma.rn.f32x2 %0, %1, %2, %3;" : "=l"(d) : "l"(a), "l"(b), "l"(c));
    return d;
}
__device__ __forceinline__ ull pack2(float lo, float hi) {
    ull d; asm("mov.b64 %0, {%1, %2};" : "=l"(d) : "f"(lo), "f"(hi)); return d;
}
__device__ __forceinline__ ull dup2(float v) {
    ull d; asm("mov.b64 %0, {%1, %1};" : "=l"(d) : "f"(v)); return d;
}
__device__ __forceinline__ float2 unpack2(ull v) {
    float lo, hi; asm("mov.b64 {%0, %1}, %2;" : "=f"(lo), "=f"(hi) : "l"(v));
    return make_float2(lo, hi);
}

struct Smem {
    ulonglong2 hist[CHUNK][33];       // [slot][j]: (pack(hs0,hs1), pack(hs2,hs3))
    ull sWif[NK][HIDDEN];             // [k][j] = (w_i, w_f)
    ull sWgo[NK][HIDDEN];             // [k][j] = (w_g, w_o)
    ull xstage[FEAT][CHUNK * 4 + 2];  // [k][t*4+s] dup'd x for NEXT chunk; row 272B
    ull xg_if[CHUNK][NS][HIDDEN];     // [t][s][j] precomputed x-gates (i,f), bias included
    ull xg_go[CHUNK][NS][HIDDEN];     // [t][s][j] (g,o)
    ull hq[2][HIDDEN][4];             // [buf][k][s] dup'd carried h
    ull wcd0[HIDDEN], wcd1[HIDDEN], wcdl[HIDDEN];
};

// Bulk x-gate phase: xg[t][s] = bias + sum_k x_s[t][k] * W_ih[:,k], for 8 staged steps.
// Two time-half passes (4 t each) keep accumulators at 32 ull (64 regs).
__device__ __forceinline__ void bulk_xgates(Smem& sm, int lane, ull bias_if, ull bias_go) {
    #pragma unroll
    for (int half = 0; half < 2; ++half) {
        ull ai[4][NS], ag[4][NS];
        #pragma unroll
        for (int tt = 0; tt < 4; ++tt)
            #pragma unroll
            for (int s = 0; s < NS; ++s) { ai[tt][s] = bias_if; ag[tt][s] = bias_go; }

        #pragma unroll
        for (int k = 0; k < NK; ++k) {
            const ull wi = sm.sWif[k][lane];
            const ull wg = sm.sWgo[k][lane];
            const ulonglong2* xr =
                reinterpret_cast<const ulonglong2*>(&sm.xstage[k][half * 16]);
            #pragma unroll
            for (int tt = 0; tt < 4; ++tt) {
                const ulonglong2 x01 = xr[tt * 2];
                const ulonglong2 x23 = xr[tt * 2 + 1];
                ai[tt][0] = fma2(x01.x, wi, ai[tt][0]); ag[tt][0] = fma2(x01.x, wg, ag[tt][0]);
                ai[tt][1] = fma2(x01.y, wi, ai[tt][1]); ag[tt][1] = fma2(x01.y, wg, ag[tt][1]);
                ai[tt][2] = fma2(x23.x, wi, ai[tt][2]); ag[tt][2] = fma2(x23.x, wg, ag[tt][2]);
                ai[tt][3] = fma2(x23.y, wi, ai[tt][3]); ag[tt][3] = fma2(x23.y, wg, ag[tt][3]);
            }
        }
        #pragma unroll
        for (int tt = 0; tt < 4; ++tt)
            #pragma unroll
            for (int s = 0; s < NS; ++s) {
                sm.xg_if[half * 4 + tt][s][lane] = ai[tt][s];
                sm.xg_go[half * 4 + tt][s][lane] = ag[tt][s];
            }
    }
}

__global__ void __launch_bounds__(32, 1)
lstm_fused_kernel(
    const float* __restrict__ x, const float* __restrict__ h0, const float* __restrict__ c0,
    const float* __restrict__ W_ih, const float* __restrict__ W_hh,
    const float* __restrict__ b_ih, const float* __restrict__ b_hh,
    const float* __restrict__ W_all, const float* __restrict__ b_all,
    const float* __restrict__ W_pos, const float* __restrict__ b_pos,
    const float* __restrict__ W_lv, const float* __restrict__ b_lv,
    float* __restrict__ out)
{
    __shared__ Smem sm;
    const int lane = threadIdx.x;
    const int s0 = blockIdx.x * NS;

    // ---- one-time init ----
    #pragma unroll
    for (int k = 0; k < NK; ++k) {
        sm.sWif[k][lane] = pack2(W_ih[lane * FEAT + k],        W_ih[(32 + lane) * FEAT + k]);
        sm.sWgo[k][lane] = pack2(W_ih[(64 + lane) * FEAT + k], W_ih[(96 + lane) * FEAT + k]);
    }
    ull whh_if[HIDDEN], whh_go[HIDDEN];   // register-resident across the whole scan
    #pragma unroll
    for (int k = 0; k < HIDDEN; ++k) {
        whh_if[k] = pack2(W_hh[lane * HIDDEN + k],        W_hh[(32 + lane) * HIDDEN + k]);
        whh_go[k] = pack2(W_hh[(64 + lane) * HIDDEN + k], W_hh[(96 + lane) * HIDDEN + k]);
    }
    // folded heads: wc = W_pos @ W_all, cb = W_pos @ b_all + b_pos
    float wc0 = 0.f, wc1 = 0.f, cb0 = b_pos[0], cb1 = b_pos[1];
    #pragma unroll
    for (int m = 0; m < HIDDEN; ++m) {
        const float wa = W_all[m * HIDDEN + lane];
        wc0 = fmaf(W_pos[m],      wa, wc0);
        wc1 = fmaf(W_pos[32 + m], wa, wc1);
        cb0 = fmaf(W_pos[m],      b_all[m], cb0);
        cb1 = fmaf(W_pos[32 + m], b_all[m], cb1);
    }
    sm.wcd0[lane] = dup2(wc0);
    sm.wcd1[lane] = dup2(wc1);
    sm.wcdl[lane] = dup2(W_lv[lane]);
    const float blv = b_lv[0];

    // Gate biases with W_ih[:,29]*1.0 folded in (mask bit == 1.0 on active steps).
    const ull bias_if = pack2(b_ih[lane]      + b_hh[lane]      + W_ih[lane * FEAT + 29],
                              b_ih[32 + lane] + b_hh[32 + lane] + W_ih[(32 + lane) * FEAT + 29]);
    const ull bias_go = pack2(b_ih[64 + lane] + b_hh[64 + lane] + W_ih[(64 + lane) * FEAT + 29],
                              b_ih[96 + lane] + b_hh[96 + lane] + W_ih[(96 + lane) * FEAT + 29]);

    const float* xb = x + (size_t)s0 * TSF;

    float h[NS], c[NS];
    #pragma unroll
    for (int s = 0; s < NS; ++s) {
        h[s] = h0[(s0 + s) * HIDDEN + lane];
        c[s] = c0[(s0 + s) * HIDDEN + lane];
    }
    #pragma unroll
    for (int s = 0; s < NS; ++s) sm.hq[0][lane][s] = dup2(h[s]);

    // Stage x for chunk 0 (steps 0..7), then bulk-compute its x-gates.
    if (lane < FEAT) {
        #pragma unroll
        for (int p = 0; p < CHUNK; ++p) {
            float xs[NS];
            #pragma unroll
            for (int s = 0; s < NS; ++s) xs[s] = xb[s * TSF + p * FEAT + lane];
            ulonglong2* xrow = reinterpret_cast<ulonglong2*>(&sm.xstage[lane][p * 4]);
            xrow[0] = make_ulonglong2(dup2(xs[0]), dup2(xs[1]));
            xrow[1] = make_ulonglong2(dup2(xs[2]), dup2(xs[3]));
        }
    }
    __syncwarp();
    bulk_xgates(sm, lane, bias_if, bias_go);
    __syncwarp();

    float* pos_out = out;                                   // [B,T,2]
    float* lv_out  = out + (size_t)BATCH * TSTEPS * 2;      // [B,T,1]
    float* hT_out  = out + (size_t)BATCH * TSTEPS * 3;      // [1,B,H]
    float* cT_out  = hT_out + BATCH * HIDDEN;               // [1,B,H]

    for (int t = 0; t < TSTEPS; ++t) {
        const int bsel = t & 1;
        const int slot = t & (CHUNK - 1);

        // Masks for THIS step (read row 29 before this step's staging overwrites it).
        const ulonglong2* mrow =
            reinterpret_cast<const ulonglong2*>(&sm.xstage[29][slot * 4]);
        const ulonglong2 m01 = mrow[0], m23 = mrow[1];
        const bool act0 = (unpack2(m01.x).x == 1.0f);
        const bool act1 = (unpack2(m01.y).x == 1.0f);
        const bool act2 = (unpack2(m23.x).x == 1.0f);
        const bool act3 = (unpack2(m23.y).x == 1.0f);

        // Prefetch x for step t+CHUNK (clamped; last-chunk staging is never consumed).
        const int tn = (t + CHUNK < TSTEPS) ? (t + CHUNK) : (TSTEPS - 1);
        float xn[NS];
        if (lane < FEAT) {
            #pragma unroll
            for (int s = 0; s < NS; ++s) xn[s] = xb[s * TSF + tn * FEAT + lane];
        }

        // Serial gates: start from precomputed x-part (+bias), add h @ W_hh.
        ull aif[NS], ago[NS];
        #pragma unroll
        for (int s = 0; s < NS; ++s) {
            aif[s] = sm.xg_if[slot][s][lane];
            ago[s] = sm.xg_go[slot][s][lane];
        }
        #pragma unroll
        for (int k = 0; k < HIDDEN; ++k) {
            const ulonglong2* hr =
                reinterpret_cast<const ulonglong2*>(&sm.hq[bsel][k][0]);
            const ulonglong2 h01 = hr[0], h23 = hr[1];
            const ull wi = whh_if[k], wg = whh_go[k];
            aif[0] = fma2(h01.x, wi, aif[0]); ago[0] = fma2(h01.x, wg, ago[0]);
            aif[1] = fma2(h01.y, wi, aif[1]); ago[1] = fma2(h01.y, wg, ago[1]);
            aif[2] = fma2(h23.x, wi, aif[2]); ago[2] = fma2(h23.x, wg, ago[2]);
            aif[3] = fma2(h23.y, wi, aif[3]); ago[3] = fma2(h23.y, wg, ago[3]);
        }

        float hs[NS];
        const bool act[NS] = {act0, act1, act2, act3};
        #pragma unroll
        for (int s = 0; s < NS; ++s) {
            const float2 g1 = unpack2(aif[s]), g2 = unpack2(ago[s]);
            const float cn = fmaf(sigf(g1.y), c[s], sigf(g1.x) * tanhap(g2.x));
            const float hn = sigf(g2.y) * tanhap(cn);
            c[s]  = act[s] ? cn : c[s];
            h[s]  = act[s] ? hn : h[s];
            hs[s] = act[s] ? hn : 0.f;
        }

        // Stores: next-h broadcast buffer, masked-h history, staged x for next chunk.
        {
            ulonglong2* hw = reinterpret_cast<ulonglong2*>(&sm.hq[bsel ^ 1][lane][0]);
            hw[0] = make_ulonglong2(dup2(h[0]), dup2(h[1]));
            hw[1] = make_ulonglong2(dup2(h[2]), dup2(h[3]));
        }
        sm.hist[slot][lane] = make_ulonglong2(pack2(hs[0], hs[1]), pack2(hs[2], hs[3]));
        if (lane < FEAT) {
            ulonglong2* xrow = reinterpret_cast<ulonglong2*>(&sm.xstage[lane][slot * 4]);
            xrow[0] = make_ulonglong2(dup2(xn[0]), dup2(xn[1]));
            xrow[1] = make_ulonglong2(dup2(xn[2]), dup2(xn[3]));
        }
        __syncwarp();

        if (slot == CHUNK - 1) {
            // Bulk head phase for the finished chunk (16 active lanes).
            if (lane < 16) {
                const int tt = lane & 7;
                const int pr = lane >> 3;                    // sample pair (2pr, 2pr+1)
                const ull* hb = reinterpret_cast<const ull*>(&sm.hist[tt][0]) + pr;
                ull p0 = 0ULL, p1 = 0ULL, pl = 0ULL;
                #pragma unroll
                for (int j = 0; j < HIDDEN; ++j) {
                    const ull hv = hb[2 * j];
                    p0 = fma2(hv, sm.wcd0[j], p0);
                    p1 = fma2(hv, sm.wcd1[j], p1);
                    pl = fma2(hv, sm.wcdl[j], pl);
                }
                const float2 q0 = unpack2(p0), q1 = unpack2(p1), ql = unpack2(pl);
                const int tg = t - (CHUNK - 1) + tt;
                const size_t oA = (size_t)(s0 + 2 * pr) * TSTEPS + tg;
                const size_t oB = oA + TSTEPS;
                reinterpret_cast<float2*>(pos_out)[oA] = make_float2(q0.x + cb0, q1.x + cb1);
                reinterpret_cast<float2*>(pos_out)[oB] = make_float2(q0.y + cb0, q1.y + cb1);
                lv_out[oA] = sigf(ql.x + blv);
                lv_out[oB] = sigf(ql.y + blv);
            }
            // Bulk x-gate phase for the next chunk.
            if (t + 1 < TSTEPS) bulk_xgates(sm, lane, bias_if, bias_go);
            __syncwarp();
        }
    }

    #pragma unroll
    for (int s = 0; s < NS; ++s) {
        hT_out[(s0 + s) * HIDDEN + lane] = h[s];
        cT_out[(s0 + s) * HIDDEN + lane] = c[s];
    }
}

extern "C" void kernel_launch(void* const* d_in, const int* in_sizes, int n_in,
                              void* d_out, int out_size)
{
    const float* x    = (const float*)d_in[0];
    const float* h0   = (const float*)d_in[1];
    const float* c0   = (const float*)d_in[2];
    const float* W_ih = (const float*)d_in[3];
    const float* W_hh = (const float*)d_in[4];
    const float* b_ih = (const float*)d_in[5];
    const float* b_hh = (const float*)d_in[6];
    const float* W_all= (const float*)d_in[7];
    const float* b_all= (const float*)d_in[8];
    const float* W_pos= (const float*)d_in[9];
    const float* b_pos= (const float*)d_in[10];
    const float* W_lv = (const float*)d_in[11];
    const float* b_lv = (const float*)d_in[12];
    float* out = (float*)d_out;

    lstm_fused_kernel<<<BATCH / NS, 32>>>(x, h0, c0, W_ih, W_hh, b_ih, b_hh,
                                          W_all, b_all, W_pos, b_pos, W_lv, b_lv, out);
}

// round 10
// speedup vs baseline: 1.5524x; 1.5524x over previous
#include <cuda_runtime.h>

#define HIDDEN 32
#define FEAT 30
#define NK 29                 /* feature 29 (mask bit) folded into bias */
#define TSTEPS 512
#define BATCH 4096
#define NS 4
#define CHUNK 16
#define TSF (TSTEPS * FEAT)

typedef unsigned long long ull;

__device__ __forceinline__ float tanhap(float x) {
    float y; asm("tanh.approx.f32 %0, %1;" : "=f"(y) : "f"(x)); return y;
}
__device__ __forceinline__ float sigf(float x) {
    return fmaf(0.5f, tanhap(0.5f * x), 0.5f);
}
__device__ __forceinline__ ull fma2(ull a, ull b, ull c) {
    ull d;
    asm("fma.rn.f32x2 %0, %1, %2, %3;" : "=l"(d) : "l"(a), "l"(b), "l"(c));
    return d;
}
__device__ __forceinline__ ull pack2(float lo, float hi) {
    ull d; asm("mov.b64 %0, {%1, %2};" : "=l"(d) : "f"(lo), "f"(hi)); return d;
}
__device__ __forceinline__ ull dup2(float v) {
    ull d; asm("mov.b64 %0, {%1, %1};" : "=l"(d) : "f"(v)); return d;
}
__device__ __forceinline__ float2 unpack2(ull v) {
    float lo, hi; asm("mov.b64 {%0, %1}, %2;" : "=f"(lo), "=f"(hi) : "l"(v));
    return make_float2(lo, hi);
}

struct Smem {
    ulonglong2 hist[CHUNK][33];   // [slot][j] = (pack(hs0,hs1), pack(hs2,hs3)), padded
    ull xq[2][HIDDEN][4];         // [buf][k][s] dup'd x (rows 0..29; row 29 = mask bit)
    ull hq[2][HIDDEN][4];         // [buf][j][s] dup'd carried h
    ulonglong2 ghat[HIDDEN];      // [j] = (pack(ĝ0,ĝ1), pack(ĝ2,ĝ3))  from warp 1
    ulonglong2 ohat[HIDDEN];      // [j] = (pack(ô0,ô1), pack(ô2,ô3))
    ull wcd0[HIDDEN], wcd1[HIDDEN], wcdl[HIDDEN];   // dup'd folded head weights
};

__global__ void __launch_bounds__(64, 1)
lstm_fused_kernel(
    const float* __restrict__ x, const float* __restrict__ h0, const float* __restrict__ c0,
    const float* __restrict__ W_ih, const float* __restrict__ W_hh,
    const float* __restrict__ b_ih, const float* __restrict__ b_hh,
    const float* __restrict__ W_all, const float* __restrict__ b_all,
    const float* __restrict__ W_pos, const float* __restrict__ b_pos,
    const float* __restrict__ W_lv, const float* __restrict__ b_lv,
    float* __restrict__ out)
{
    __shared__ Smem sm;
    const int tid  = threadIdx.x;
    const int lane = tid & 31;
    const int wid  = tid >> 5;          // warp 0: gates (i,f); warp 1: gates (g,o)
    const int gb   = wid * 64;          // gate-pair row base in 4H weight matrices
    const int s0   = blockIdx.x * NS;

    // Per-warp gate-half weights, fully register-resident (61 ulls = 122 regs).
    ull wih[NK], whh[HIDDEN];
    #pragma unroll
    for (int k = 0; k < NK; ++k)
        wih[k] = pack2(W_ih[(gb + lane) * FEAT + k], W_ih[(gb + 32 + lane) * FEAT + k]);
    #pragma unroll
    for (int k = 0; k < HIDDEN; ++k)
        whh[k] = pack2(W_hh[(gb + lane) * HIDDEN + k], W_hh[(gb + 32 + lane) * HIDDEN + k]);

    // Gate-pair bias with mask-bit column (W_ih[:,29] * 1.0) folded in.
    const ull bias = pack2(
        b_ih[gb + lane]      + b_hh[gb + lane]      + W_ih[(gb + lane) * FEAT + 29],
        b_ih[gb + 32 + lane] + b_hh[gb + 32 + lane] + W_ih[(gb + 32 + lane) * FEAT + 29]);

    // Folded heads: wc = W_pos @ W_all, cb = W_pos @ b_all + b_pos.
    float wc0 = 0.f, wc1 = 0.f, cb0 = b_pos[0], cb1 = b_pos[1];
    #pragma unroll
    for (int m = 0; m < HIDDEN; ++m) {
        const float wa = W_all[m * HIDDEN + lane];
        wc0 = fmaf(W_pos[m],      wa, wc0);
        wc1 = fmaf(W_pos[32 + m], wa, wc1);
        cb0 = fmaf(W_pos[m],      b_all[m], cb0);
        cb1 = fmaf(W_pos[32 + m], b_all[m], cb1);
    }
    const float blv = b_lv[0];

    const float* xb = x + (size_t)s0 * TSF;

    float h[NS], c[NS];
    if (wid == 0) {
        sm.wcd0[lane] = dup2(wc0);
        sm.wcd1[lane] = dup2(wc1);
        sm.wcdl[lane] = dup2(W_lv[lane]);
        #pragma unroll
        for (int s = 0; s < NS; ++s) {
            h[s] = h0[(s0 + s) * HIDDEN + lane];
            c[s] = c0[(s0 + s) * HIDDEN + lane];
            sm.hq[0][lane][s] = dup2(h[s]);
        }
    } else if (lane < FEAT) {
        #pragma unroll
        for (int s = 0; s < NS; ++s)
            sm.xq[0][lane][s] = dup2(xb[s * TSF + lane]);
    }
    __syncthreads();

    float* pos_out = out;                                   // [B,T,2]
    float* lv_out  = out + (size_t)BATCH * TSTEPS * 2;      // [B,T,1]
    float* hT_out  = out + (size_t)BATCH * TSTEPS * 3;      // [1,B,H]
    float* cT_out  = hT_out + BATCH * HIDDEN;               // [1,B,H]

    for (int t = 0; t < TSTEPS; ++t) {
        const int bsel = t & 1;
        const int slot = t & (CHUNK - 1);

        // Phase 1 (both warps): gate-pair accumulation, all weights in registers.
        ull ag[NS];
        #pragma unroll
        for (int s = 0; s < NS; ++s) ag[s] = bias;

        #pragma unroll
        for (int k = 0; k < NK; ++k) {
            const ulonglong2* xr = reinterpret_cast<const ulonglong2*>(&sm.xq[bsel][k][0]);
            const ulonglong2 x01 = xr[0], x23 = xr[1];
            const ull w = wih[k];
            ag[0] = fma2(x01.x, w, ag[0]);
            ag[1] = fma2(x01.y, w, ag[1]);
            ag[2] = fma2(x23.x, w, ag[2]);
            ag[3] = fma2(x23.y, w, ag[3]);
        }
        #pragma unroll
        for (int k = 0; k < HIDDEN; ++k) {
            const ulonglong2* hr = reinterpret_cast<const ulonglong2*>(&sm.hq[bsel][k][0]);
            const ulonglong2 h01 = hr[0], h23 = hr[1];
            const ull w = whh[k];
            ag[0] = fma2(h01.x, w, ag[0]);
            ag[1] = fma2(h01.y, w, ag[1]);
            ag[2] = fma2(h23.x, w, ag[2]);
            ag[3] = fma2(h23.y, w, ag[3]);
        }

        // Phase 2: warp 1 publishes tanh(g), sig(o); warp 0 pre-computes sig(i), sig(f).
        float isg[NS], fsg[NS];
        bool act[NS];
        if (wid == 1) {
            float gh[NS], oh[NS];
            #pragma unroll
            for (int s = 0; s < NS; ++s) {
                const float2 g = unpack2(ag[s]);
                gh[s] = tanhap(g.x);
                oh[s] = sigf(g.y);
            }
            sm.ghat[lane] = make_ulonglong2(pack2(gh[0], gh[1]), pack2(gh[2], gh[3]));
            sm.ohat[lane] = make_ulonglong2(pack2(oh[0], oh[1]), pack2(oh[2], oh[3]));
        } else {
            #pragma unroll
            for (int s = 0; s < NS; ++s) {
                const float2 g = unpack2(ag[s]);
                isg[s] = sigf(g.x);
                fsg[s] = sigf(g.y);
                act[s] = (unpack2(sm.xq[bsel][29][s]).x == 1.0f);
            }
        }
        __syncthreads();

        // Phase 3: warp 0 combines + publishes h; warp 1 stages next-step x.
        if (wid == 0) {
            const ulonglong2 gq = sm.ghat[lane], oq = sm.ohat[lane];
            const float2 g01 = unpack2(gq.x), g23 = unpack2(gq.y);
            const float2 o01 = unpack2(oq.x), o23 = unpack2(oq.y);
            const float gh[NS] = {g01.x, g01.y, g23.x, g23.y};
            const float oh[NS] = {o01.x, o01.y, o23.x, o23.y};
            float hs[NS];
            #pragma unroll
            for (int s = 0; s < NS; ++s) {
                const float cn = fmaf(fsg[s], c[s], isg[s] * gh[s]);
                const float hn = oh[s] * tanhap(cn);
                c[s]  = act[s] ? cn : c[s];
                h[s]  = act[s] ? hn : h[s];
                hs[s] = act[s] ? hn : 0.f;
            }
            ulonglong2* hw = reinterpret_cast<ulonglong2*>(&sm.hq[bsel ^ 1][lane][0]);
            hw[0] = make_ulonglong2(dup2(h[0]), dup2(h[1]));
            hw[1] = make_ulonglong2(dup2(h[2]), dup2(h[3]));
            sm.hist[slot][lane] =
                make_ulonglong2(pack2(hs[0], hs[1]), pack2(hs[2], hs[3]));
        } else if (lane < FEAT) {
            const int tn = (t + 1 < TSTEPS) ? (t + 1) : t;   // clamped (tail unread)
            const int o = tn * FEAT + lane;
            ulonglong2* xw = reinterpret_cast<ulonglong2*>(&sm.xq[bsel ^ 1][lane][0]);
            xw[0] = make_ulonglong2(dup2(xb[0 * TSF + o]), dup2(xb[1 * TSF + o]));
            xw[1] = make_ulonglong2(dup2(xb[2 * TSF + o]), dup2(xb[3 * TSF + o]));
        }
        __syncthreads();

        // Bulk head phase over the finished 16-step chunk (warp 0; no bars inside).
        if (slot == CHUNK - 1 && wid == 0) {
            const int tt = lane & 15;
            const int pr = lane >> 4;                        // sample pair (2pr, 2pr+1)
            const ull* hrow = reinterpret_cast<const ull*>(&sm.hist[tt][0]) + pr;
            ull p0 = 0ULL, p1 = 0ULL, pl = 0ULL;
            #pragma unroll
            for (int j = 0; j < HIDDEN; ++j) {
                const ull hv = hrow[j * 2];
                p0 = fma2(hv, sm.wcd0[j], p0);
                p1 = fma2(hv, sm.wcd1[j], p1);
                pl = fma2(hv, sm.wcdl[j], pl);
            }
            const float2 q0 = unpack2(p0), q1 = unpack2(p1), ql = unpack2(pl);
            const int tg = t - (CHUNK - 1) + tt;
            const size_t oA = (size_t)(s0 + 2 * pr) * TSTEPS + tg;
            const size_t oB = oA + TSTEPS;
            reinterpret_cast<float2*>(pos_out)[oA] = make_float2(q0.x + cb0, q1.x + cb1);
            reinterpret_cast<float2*>(pos_out)[oB] = make_float2(q0.y + cb0, q1.y + cb1);
            lv_out[oA] = sigf(ql.x + blv);
            lv_out[oB] = sigf(ql.y + blv);
        }
    }

    if (wid == 0) {
        #pragma unroll
        for (int s = 0; s < NS; ++s) {
            hT_out[(s0 + s) * HIDDEN + lane] = h[s];
            cT_out[(s0 + s) * HIDDEN + lane] = c[s];
        }
    }
}

extern "C" void kernel_launch(void* const* d_in, const int* in_sizes, int n_in,
                              void* d_out, int out_size)
{
    const float* x    = (const float*)d_in[0];
    const float* h0   = (const float*)d_in[1];
    const float* c0   = (const float*)d_in[2];
    const float* W_ih = (const float*)d_in[3];
    const float* W_hh = (const float*)d_in[4];
    const float* b_ih = (const float*)d_in[5];
    const float* b_hh = (const float*)d_in[6];
    const float* W_all= (const float*)d_in[7];
    const float* b_all= (const float*)d_in[8];
    const float* W_pos= (const float*)d_in[9];
    const float* b_pos= (const float*)d_in[10];
    const float* W_lv = (const float*)d_in[11];
    const float* b_lv = (const float*)d_in[12];
    float* out = (float*)d_out;

    lstm_fused_kernel<<<BATCH / NS, 64>>>(x, h0, c0, W_ih, W_hh, b_ih, b_hh,
                                          W_all, b_all, W_pos, b_pos, W_lv, b_lv, out);
}

// round 11
// speedup vs baseline: 1.5572x; 1.0031x over previous
#include <cuda_runtime.h>

#define HIDDEN 32
#define FEAT 30
#define NK 29                 /* feature 29 (mask bit) folded into bias */
#define TSTEPS 512
#define BATCH 4096
#define NS 8                  /* samples per block */
#define CHUNK 8
#define TSF (TSTEPS * FEAT)

typedef unsigned long long ull;

__device__ __forceinline__ float tanhap(float x) {
    float y; asm("tanh.approx.f32 %0, %1;" : "=f"(y) : "f"(x)); return y;
}
__device__ __forceinline__ float sigf(float x) {
    return fmaf(0.5f, tanhap(0.5f * x), 0.5f);
}
__device__ __forceinline__ ull fma2(ull a, ull b, ull c) {
    ull d;
    asm("fma.rn.f32x2 %0, %1, %2, %3;" : "=l"(d) : "l"(a), "l"(b), "l"(c));
    return d;
}
__device__ __forceinline__ ull pack2(float lo, float hi) {
    ull d; asm("mov.b64 %0, {%1, %2};" : "=l"(d) : "f"(lo), "f"(hi)); return d;
}
__device__ __forceinline__ ull dup2(float v) {
    ull d; asm("mov.b64 %0, {%1, %1};" : "=l"(d) : "f"(v)); return d;
}
__device__ __forceinline__ float2 unpack2(ull v) {
    float lo, hi; asm("mov.b64 {%0, %1}, %2;" : "=f"(lo), "=f"(hi) : "l"(v));
    return make_float2(lo, hi);
}

struct Smem {
    ull xq[2][HIDDEN][NS];        // [buf][k][s] dup'd x (rows 0..29; row 29 = mask)
    ull hq[2][HIDDEN][NS];        // [buf][j][s] dup'd carried h
    ull ex[2][HIDDEN][4];         // [src warp][j][s] activated foreign gate pairs
    ull hist[CHUNK][HIDDEN][4];   // [slot][j][pair] pack2 masked-h sample pairs
    ull wcd0[HIDDEN], wcd1[HIDDEN], wcdl[HIDDEN];
};

__global__ void __launch_bounds__(64, 1)
lstm_fused_kernel(
    const float* __restrict__ x, const float* __restrict__ h0, const float* __restrict__ c0,
    const float* __restrict__ W_ih, const float* __restrict__ W_hh,
    const float* __restrict__ b_ih, const float* __restrict__ b_hh,
    const float* __restrict__ W_all, const float* __restrict__ b_all,
    const float* __restrict__ W_pos, const float* __restrict__ b_pos,
    const float* __restrict__ W_lv, const float* __restrict__ b_lv,
    float* __restrict__ out)
{
    __shared__ Smem sm;
    const int tid  = threadIdx.x;
    const int lane = tid & 31;
    const int wid  = tid >> 5;      // warp 0: gates (i,f); warp 1: gates (g,o)
    const int gb   = wid * 64;      // gate-pair row base in 4H weights
    const int ob   = wid * 4;       // owned-sample base (state/combine/heads)
    const int s0   = blockIdx.x * NS;

    // Per-warp gate-half weights, register-resident (61 ulls = 122 regs).
    ull wih[NK], whh[HIDDEN];
    #pragma unroll
    for (int k = 0; k < NK; ++k)
        wih[k] = pack2(W_ih[(gb + lane) * FEAT + k], W_ih[(gb + 32 + lane) * FEAT + k]);
    #pragma unroll
    for (int k = 0; k < HIDDEN; ++k)
        whh[k] = pack2(W_hh[(gb + lane) * HIDDEN + k], W_hh[(gb + 32 + lane) * HIDDEN + k]);

    const ull bias = pack2(
        b_ih[gb + lane]      + b_hh[gb + lane]      + W_ih[(gb + lane) * FEAT + 29],
        b_ih[gb + 32 + lane] + b_hh[gb + 32 + lane] + W_ih[(gb + 32 + lane) * FEAT + 29]);

    // Folded heads: wc = W_pos @ W_all, cb = W_pos @ b_all + b_pos.
    float wc0 = 0.f, wc1 = 0.f, cb0 = b_pos[0], cb1 = b_pos[1];
    #pragma unroll
    for (int m = 0; m < HIDDEN; ++m) {
        const float wa = W_all[m * HIDDEN + lane];
        wc0 = fmaf(W_pos[m],      wa, wc0);
        wc1 = fmaf(W_pos[32 + m], wa, wc1);
        cb0 = fmaf(W_pos[m],      b_all[m], cb0);
        cb1 = fmaf(W_pos[32 + m], b_all[m], cb1);
    }
    const float blv = b_lv[0];
    if (wid == 0) {
        sm.wcd0[lane] = dup2(wc0);
        sm.wcd1[lane] = dup2(wc1);
        sm.wcdl[lane] = dup2(W_lv[lane]);
    }

    // Own-sample state + initial staging (each warp handles its 4 samples).
    const float* xob = x + (size_t)(s0 + ob) * TSF;
    float h[4], c[4];
    #pragma unroll
    for (int s = 0; s < 4; ++s) {
        h[s] = h0[(s0 + ob + s) * HIDDEN + lane];
        c[s] = c0[(s0 + ob + s) * HIDDEN + lane];
    }
    {
        ulonglong2* hw = reinterpret_cast<ulonglong2*>(&sm.hq[0][lane][ob]);
        hw[0] = make_ulonglong2(dup2(h[0]), dup2(h[1]));
        hw[1] = make_ulonglong2(dup2(h[2]), dup2(h[3]));
        if (lane < FEAT) {
            ulonglong2* xw = reinterpret_cast<ulonglong2*>(&sm.xq[0][lane][ob]);
            xw[0] = make_ulonglong2(dup2(xob[lane]),           dup2(xob[TSF + lane]));
            xw[1] = make_ulonglong2(dup2(xob[2 * TSF + lane]), dup2(xob[3 * TSF + lane]));
        }
    }
    __syncthreads();

    // Activation shape for this warp's first gate: wid0 -> sigmoid, wid1 -> tanh.
    const float a_m  = wid ? 1.0f : 0.5f;   // argument scale
    const float a_sc = wid ? 1.0f : 0.5f;   // output scale
    const float a_of = wid ? 0.0f : 0.5f;   // output offset

    float* pos_out = out;                                   // [B,T,2]
    float* lv_out  = out + (size_t)BATCH * TSTEPS * 2;      // [B,T,1]
    float* hT_out  = out + (size_t)BATCH * TSTEPS * 3;      // [1,B,H]
    float* cT_out  = hT_out + BATCH * HIDDEN;               // [1,B,H]

    for (int t = 0; t < TSTEPS; ++t) {
        const int bsel = t & 1;
        const int slot = t & (CHUNK - 1);

        // Prefetch next x for own samples (clamped; tail staging never consumed).
        const int tn = (t + 1 < TSTEPS) ? (t + 1) : t;
        float xn[4];
        if (lane < FEAT) {
            const int o = tn * FEAT + lane;
            #pragma unroll
            for (int s = 0; s < 4; ++s) xn[s] = xob[s * TSF + o];
        }

        // Phase 1: this warp's gate pair for ALL 8 samples (weights in registers).
        ull ag[NS];
        #pragma unroll
        for (int s = 0; s < NS; ++s) ag[s] = bias;

        #pragma unroll
        for (int k = 0; k < NK; ++k) {
            const ulonglong2* xr = reinterpret_cast<const ulonglong2*>(&sm.xq[bsel][k][0]);
            const ulonglong2 p0 = xr[0], p1 = xr[1], p2 = xr[2], p3 = xr[3];
            const ull w = wih[k];
            ag[0] = fma2(p0.x, w, ag[0]); ag[1] = fma2(p0.y, w, ag[1]);
            ag[2] = fma2(p1.x, w, ag[2]); ag[3] = fma2(p1.y, w, ag[3]);
            ag[4] = fma2(p2.x, w, ag[4]); ag[5] = fma2(p2.y, w, ag[5]);
            ag[6] = fma2(p3.x, w, ag[6]); ag[7] = fma2(p3.y, w, ag[7]);
        }
        #pragma unroll
        for (int k = 0; k < HIDDEN; ++k) {
            const ulonglong2* hr = reinterpret_cast<const ulonglong2*>(&sm.hq[bsel][k][0]);
            const ulonglong2 p0 = hr[0], p1 = hr[1], p2 = hr[2], p3 = hr[3];
            const ull w = whh[k];
            ag[0] = fma2(p0.x, w, ag[0]); ag[1] = fma2(p0.y, w, ag[1]);
            ag[2] = fma2(p1.x, w, ag[2]); ag[3] = fma2(p1.y, w, ag[3]);
            ag[4] = fma2(p2.x, w, ag[4]); ag[5] = fma2(p2.y, w, ag[5]);
            ag[6] = fma2(p3.x, w, ag[6]); ag[7] = fma2(p3.y, w, ag[7]);
        }

        // Phase 2: activate; publish foreign-sample halves for the other warp.
        float a1[NS], a2[NS];
        #pragma unroll
        for (int s = 0; s < NS; ++s) {
            const float2 g = unpack2(ag[s]);
            a1[s] = fmaf(a_sc, tanhap(a_m * g.x), a_of);  // sig(i) | tanh(g)
            a2[s] = sigf(g.y);                            // sig(f) | sig(o)
        }
        {
            const int fs = 4 - ob;   // foreign base: wid0 -> 4, wid1 -> 0
            ulonglong2* ew = reinterpret_cast<ulonglong2*>(&sm.ex[wid][lane][0]);
            ew[0] = make_ulonglong2(pack2(a1[fs],     a2[fs]),
                                    pack2(a1[fs + 1], a2[fs + 1]));
            ew[1] = make_ulonglong2(pack2(a1[fs + 2], a2[fs + 2]),
                                    pack2(a1[fs + 3], a2[fs + 3]));
        }
        __syncthreads();

        // Phase 3: combine for OWN samples; publish h; stage x.
        float f1[4], f2[4];
        {
            const ulonglong2* er =
                reinterpret_cast<const ulonglong2*>(&sm.ex[1 - wid][lane][0]);
            const ulonglong2 e0 = er[0], e1 = er[1];
            const float2 u0 = unpack2(e0.x), u1 = unpack2(e0.y);
            const float2 u2 = unpack2(e1.x), u3 = unpack2(e1.y);
            f1[0] = u0.x; f2[0] = u0.y; f1[1] = u1.x; f2[1] = u1.y;
            f1[2] = u2.x; f2[2] = u2.y; f1[3] = u3.x; f2[3] = u3.y;
        }
        bool act[4];
        {
            const ulonglong2* mr =
                reinterpret_cast<const ulonglong2*>(&sm.xq[bsel][29][ob]);
            const ulonglong2 m0 = mr[0], m1 = mr[1];
            act[0] = (unpack2(m0.x).x == 1.0f);
            act[1] = (unpack2(m0.y).x == 1.0f);
            act[2] = (unpack2(m1.x).x == 1.0f);
            act[3] = (unpack2(m1.y).x == 1.0f);
        }
        float hs[4];
        #pragma unroll
        for (int s = 0; s < 4; ++s) {
            const float isg = wid ? f1[s] : a1[ob + s];
            const float fsg = wid ? f2[s] : a2[ob + s];
            const float gth = wid ? a1[ob + s] : f1[s];
            const float osg = wid ? a2[ob + s] : f2[s];
            const float cn = fmaf(fsg, c[s], isg * gth);
            const float hn = osg * tanhap(cn);
            c[s]  = act[s] ? cn : c[s];
            h[s]  = act[s] ? hn : h[s];
            hs[s] = act[s] ? hn : 0.f;
        }
        {
            ulonglong2* hw = reinterpret_cast<ulonglong2*>(&sm.hq[bsel ^ 1][lane][ob]);
            hw[0] = make_ulonglong2(dup2(h[0]), dup2(h[1]));
            hw[1] = make_ulonglong2(dup2(h[2]), dup2(h[3]));
            *reinterpret_cast<ulonglong2*>(&sm.hist[slot][lane][2 * wid]) =
                make_ulonglong2(pack2(hs[0], hs[1]), pack2(hs[2], hs[3]));
            if (lane < FEAT) {
                ulonglong2* xw = reinterpret_cast<ulonglong2*>(&sm.xq[bsel ^ 1][lane][ob]);
                xw[0] = make_ulonglong2(dup2(xn[0]), dup2(xn[1]));
                xw[1] = make_ulonglong2(dup2(xn[2]), dup2(xn[3]));
            }
        }
        __syncthreads();

        // Head phase per finished chunk: each warp covers its own 2 sample pairs.
        if (slot == CHUNK - 1 && lane < 16) {
            const int tt = lane & 7;
            const int pr = lane >> 3;
            const int gp = 2 * wid + pr;                 // global pair (samples 2gp,2gp+1)
            const ull* hb = &sm.hist[tt][0][gp];
            ull p0 = 0ULL, p1 = 0ULL, pl = 0ULL;
            #pragma unroll
            for (int j = 0; j < HIDDEN; ++j) {
                const ull hv = hb[j * 4];
                p0 = fma2(hv, sm.wcd0[j], p0);
                p1 = fma2(hv, sm.wcd1[j], p1);
                pl = fma2(hv, sm.wcdl[j], pl);
            }
            const float2 q0 = unpack2(p0), q1 = unpack2(p1), ql = unpack2(pl);
            const int tg = t - (CHUNK - 1) + tt;
            const size_t oA = (size_t)(s0 + 2 * gp) * TSTEPS + tg;
            const size_t oB = oA + TSTEPS;
            reinterpret_cast<float2*>(pos_out)[oA] = make_float2(q0.x + cb0, q1.x + cb1);
            reinterpret_cast<float2*>(pos_out)[oB] = make_float2(q0.y + cb0, q1.y + cb1);
            lv_out[oA] = sigf(ql.x + blv);
            lv_out[oB] = sigf(ql.y + blv);
        }
    }

    #pragma unroll
    for (int s = 0; s < 4; ++s) {
        hT_out[(s0 + ob + s) * HIDDEN + lane] = h[s];
        cT_out[(s0 + ob + s) * HIDDEN + lane] = c[s];
    }
}

extern "C" void kernel_launch(void* const* d_in, const int* in_sizes, int n_in,
                              void* d_out, int out_size)
{
    const float* x    = (const float*)d_in[0];
    const float* h0   = (const float*)d_in[1];
    const float* c0   = (const float*)d_in[2];
    const float* W_ih = (const float*)d_in[3];
    const float* W_hh = (const float*)d_in[4];
    const float* b_ih = (const float*)d_in[5];
    const float* b_hh = (const float*)d_in[6];
    const float* W_all= (const float*)d_in[7];
    const float* b_all= (const float*)d_in[8];
    const float* W_pos= (const float*)d_in[9];
    const float* b_pos= (const float*)d_in[10];
    const float* W_lv = (const float*)d_in[11];
    const float* b_lv = (const float*)d_in[12];
    float* out = (float*)d_out;

    lstm_fused_kernel<<<BATCH / NS, 64>>>(x, h0, c0, W_ih, W_hh, b_ih, b_hh,
                                          W_all, b_all, W_pos, b_pos, W_lv, b_lv, out);
}

// round 12
// speedup vs baseline: 1.9518x; 1.2534x over previous
#include <cuda_runtime.h>

#define HIDDEN 32
#define FEAT 30
#define NK 29                 /* feature 29 (mask bit) folded into bias */
#define TSTEPS 512
#define BATCH 4096
#define NS 8                  /* samples per block (4 owned per warp) */
#define CHUNK 8
#define XSTR 10               /* ull row stride for xq/hq: 80B -> conflict-free */
#define ESTR 6                /* ull row stride for ex: 48B -> conflict-free */
#define TSF (TSTEPS * FEAT)

typedef unsigned long long ull;

__device__ __forceinline__ float tanhap(float x) {
    float y; asm("tanh.approx.f32 %0, %1;" : "=f"(y) : "f"(x)); return y;
}
__device__ __forceinline__ float sigf(float x) {
    return fmaf(0.5f, tanhap(0.5f * x), 0.5f);
}
__device__ __forceinline__ ull fma2(ull a, ull b, ull c) {
    ull d;
    asm("fma.rn.f32x2 %0, %1, %2, %3;" : "=l"(d) : "l"(a), "l"(b), "l"(c));
    return d;
}
__device__ __forceinline__ ull pack2(float lo, float hi) {
    ull d; asm("mov.b64 %0, {%1, %2};" : "=l"(d) : "f"(lo), "f"(hi)); return d;
}
__device__ __forceinline__ ull dup2(float v) {
    ull d; asm("mov.b64 %0, {%1, %1};" : "=l"(d) : "f"(v)); return d;
}
__device__ __forceinline__ float2 unpack2(ull v) {
    float lo, hi; asm("mov.b64 {%0, %1}, %2;" : "=f"(lo), "=f"(hi) : "l"(v));
    return make_float2(lo, hi);
}

struct Smem {
    ull xq[2][HIDDEN * XSTR];     // [buf][k*XSTR + s] dup'd x (row 29 = mask bit)
    ull hq[2][HIDDEN * XSTR];     // [buf][j*XSTR + s] dup'd carried h
    ull ex[2][HIDDEN * ESTR];     // [src warp][lane*ESTR + s] activated gate pairs
    ull hist[CHUNK][4][HIDDEN + 1]; // [slot][pair][j] pack2 masked-h sample pairs
    ull wcd0[HIDDEN], wcd1[HIDDEN], wcdl[HIDDEN];
};

// Gate-pair accumulation + activation for one 4-sample quad.
__device__ __forceinline__ void gate_quad(
    const ull* __restrict__ xbase, const ull* __restrict__ hbase,
    const ull* wih, const ull* whh, ull bias,
    float a_m, float a_sc, float a_of,
    float* o1, float* o2)
{
    ull ag0 = bias, ag1 = bias, ag2 = bias, ag3 = bias;
    #pragma unroll
    for (int k = 0; k < NK; ++k) {
        const ulonglong2 v01 = *reinterpret_cast<const ulonglong2*>(xbase + k * XSTR);
        const ulonglong2 v23 = *reinterpret_cast<const ulonglong2*>(xbase + k * XSTR + 2);
        const ull w = wih[k];
        ag0 = fma2(v01.x, w, ag0); ag1 = fma2(v01.y, w, ag1);
        ag2 = fma2(v23.x, w, ag2); ag3 = fma2(v23.y, w, ag3);
    }
    #pragma unroll
    for (int k = 0; k < HIDDEN; ++k) {
        const ulonglong2 v01 = *reinterpret_cast<const ulonglong2*>(hbase + k * XSTR);
        const ulonglong2 v23 = *reinterpret_cast<const ulonglong2*>(hbase + k * XSTR + 2);
        const ull w = whh[k];
        ag0 = fma2(v01.x, w, ag0); ag1 = fma2(v01.y, w, ag1);
        ag2 = fma2(v23.x, w, ag2); ag3 = fma2(v23.y, w, ag3);
    }
    const float2 g0 = unpack2(ag0), g1 = unpack2(ag1);
    const float2 g2 = unpack2(ag2), g3 = unpack2(ag3);
    o1[0] = fmaf(a_sc, tanhap(a_m * g0.x), a_of); o2[0] = sigf(g0.y);
    o1[1] = fmaf(a_sc, tanhap(a_m * g1.x), a_of); o2[1] = sigf(g1.y);
    o1[2] = fmaf(a_sc, tanhap(a_m * g2.x), a_of); o2[2] = sigf(g2.y);
    o1[3] = fmaf(a_sc, tanhap(a_m * g3.x), a_of); o2[3] = sigf(g3.y);
}

__global__ void __launch_bounds__(64, 1)
lstm_fused_kernel(
    const float* __restrict__ x, const float* __restrict__ h0, const float* __restrict__ c0,
    const float* __restrict__ W_ih, const float* __restrict__ W_hh,
    const float* __restrict__ b_ih, const float* __restrict__ b_hh,
    const float* __restrict__ W_all, const float* __restrict__ b_all,
    const float* __restrict__ W_pos, const float* __restrict__ b_pos,
    const float* __restrict__ W_lv, const float* __restrict__ b_lv,
    float* __restrict__ out)
{
    __shared__ Smem sm;
    const int tid  = threadIdx.x;
    const int lane = tid & 31;
    const int wid  = tid >> 5;      // warp 0: gates (i,f); warp 1: gates (g,o)
    const int gb   = wid * 64;      // gate-pair row base in 4H weights
    const int ob   = wid * 4;       // own-sample base
    const int fb   = 4 - ob;        // foreign-sample base
    const int s0   = blockIdx.x * NS;

    // Per-warp gate-half weights, register-resident (61 ulls = 122 regs).
    ull wih[NK], whh[HIDDEN];
    #pragma unroll
    for (int k = 0; k < NK; ++k)
        wih[k] = pack2(W_ih[(gb + lane) * FEAT + k], W_ih[(gb + 32 + lane) * FEAT + k]);
    #pragma unroll
    for (int k = 0; k < HIDDEN; ++k)
        whh[k] = pack2(W_hh[(gb + lane) * HIDDEN + k], W_hh[(gb + 32 + lane) * HIDDEN + k]);

    const ull bias = pack2(
        b_ih[gb + lane]      + b_hh[gb + lane]      + W_ih[(gb + lane) * FEAT + 29],
        b_ih[gb + 32 + lane] + b_hh[gb + 32 + lane] + W_ih[(gb + 32 + lane) * FEAT + 29]);

    // Folded heads: wc = W_pos @ W_all, cb = W_pos @ b_all + b_pos.
    float wc0 = 0.f, wc1 = 0.f, cb0 = b_pos[0], cb1 = b_pos[1];
    #pragma unroll
    for (int m = 0; m < HIDDEN; ++m) {
        const float wa = W_all[m * HIDDEN + lane];
        wc0 = fmaf(W_pos[m],      wa, wc0);
        wc1 = fmaf(W_pos[32 + m], wa, wc1);
        cb0 = fmaf(W_pos[m],      b_all[m], cb0);
        cb1 = fmaf(W_pos[32 + m], b_all[m], cb1);
    }
    const float blv = b_lv[0];
    if (wid == 0) {
        sm.wcd0[lane] = dup2(wc0);
        sm.wcd1[lane] = dup2(wc1);
        sm.wcdl[lane] = dup2(W_lv[lane]);
    }

    // Activation shape: warp0 first gate = sigmoid, warp1 first gate = tanh.
    const float a_m  = wid ? 1.0f : 0.5f;
    const float a_sc = wid ? 1.0f : 0.5f;
    const float a_of = wid ? 0.0f : 0.5f;

    // Own-sample state + initial staging.
    const float* xob = x + (size_t)(s0 + ob) * TSF;
    float h[4], c[4];
    #pragma unroll
    for (int s = 0; s < 4; ++s) {
        h[s] = h0[(s0 + ob + s) * HIDDEN + lane];
        c[s] = c0[(s0 + ob + s) * HIDDEN + lane];
    }
    {
        ulonglong2* hw = reinterpret_cast<ulonglong2*>(&sm.hq[0][lane * XSTR + ob]);
        hw[0] = make_ulonglong2(dup2(h[0]), dup2(h[1]));
        hw[1] = make_ulonglong2(dup2(h[2]), dup2(h[3]));
        if (lane < FEAT) {
            ulonglong2* xw = reinterpret_cast<ulonglong2*>(&sm.xq[0][lane * XSTR + ob]);
            xw[0] = make_ulonglong2(dup2(xob[lane]),           dup2(xob[TSF + lane]));
            xw[1] = make_ulonglong2(dup2(xob[2 * TSF + lane]), dup2(xob[3 * TSF + lane]));
        }
    }
    __syncthreads();

    float* pos_out = out;                                   // [B,T,2]
    float* lv_out  = out + (size_t)BATCH * TSTEPS * 2;      // [B,T,1]
    float* hT_out  = out + (size_t)BATCH * TSTEPS * 3;      // [1,B,H]
    float* cT_out  = hT_out + BATCH * HIDDEN;               // [1,B,H]

    for (int t = 0; t < TSTEPS; ++t) {
        const int bsel = t & 1;
        const int slot = t & (CHUNK - 1);

        // Prefetch next x for own samples (clamped; tail staging never consumed).
        const int tn = (t + 1 < TSTEPS) ? (t + 1) : t;
        float xn[4];
        if (lane < FEAT) {
            const int o = tn * FEAT + lane;
            #pragma unroll
            for (int s = 0; s < 4; ++s) xn[s] = xob[s * TSF + o];
        }

        // Masks for own quad (broadcast reads of dup'd row 29).
        bool act[4];
        {
            const ulonglong2* mr =
                reinterpret_cast<const ulonglong2*>(&sm.xq[bsel][29 * XSTR + ob]);
            const ulonglong2 m0 = mr[0], m1 = mr[1];
            act[0] = (unpack2(m0.x).x == 1.0f);
            act[1] = (unpack2(m0.y).x == 1.0f);
            act[2] = (unpack2(m1.x).x == 1.0f);
            act[3] = (unpack2(m1.y).x == 1.0f);
        }

        // Pass 1: FOREIGN quad -> activate -> publish to exchange (accums die here).
        {
            float f1[4], f2[4];
            gate_quad(&sm.xq[bsel][fb], &sm.hq[bsel][fb], wih, whh, bias,
                      a_m, a_sc, a_of, f1, f2);
            ulonglong2* ew = reinterpret_cast<ulonglong2*>(&sm.ex[wid][lane * ESTR]);
            ew[0] = make_ulonglong2(pack2(f1[0], f2[0]), pack2(f1[1], f2[1]));
            ew[1] = make_ulonglong2(pack2(f1[2], f2[2]), pack2(f1[3], f2[3]));
        }

        // Pass 2: OWN quad (kept in registers).
        float o1[4], o2[4];
        gate_quad(&sm.xq[bsel][ob], &sm.hq[bsel][ob], wih, whh, bias,
                  a_m, a_sc, a_of, o1, o2);
        __syncthreads();

        // Combine for own samples using the other warp's published pair.
        float hs[4];
        {
            const ulonglong2* er =
                reinterpret_cast<const ulonglong2*>(&sm.ex[1 - wid][lane * ESTR]);
            const ulonglong2 e0 = er[0], e1 = er[1];
            const float2 u[4] = {unpack2(e0.x), unpack2(e0.y),
                                 unpack2(e1.x), unpack2(e1.y)};
            #pragma unroll
            for (int s = 0; s < 4; ++s) {
                const float isg = wid ? u[s].x : o1[s];
                const float fsg = wid ? u[s].y : o2[s];
                const float gth = wid ? o1[s] : u[s].x;
                const float osg = wid ? o2[s] : u[s].y;
                const float cn = fmaf(fsg, c[s], isg * gth);
                const float hn = osg * tanhap(cn);
                c[s]  = act[s] ? cn : c[s];
                h[s]  = act[s] ? hn : h[s];
                hs[s] = act[s] ? hn : 0.f;
            }
        }

        // Publish h, history, staged x.
        {
            ulonglong2* hw = reinterpret_cast<ulonglong2*>(
                &sm.hq[bsel ^ 1][lane * XSTR + ob]);
            hw[0] = make_ulonglong2(dup2(h[0]), dup2(h[1]));
            hw[1] = make_ulonglong2(dup2(h[2]), dup2(h[3]));
            sm.hist[slot][2 * wid + 0][lane] = pack2(hs[0], hs[1]);
            sm.hist[slot][2 * wid + 1][lane] = pack2(hs[2], hs[3]);
            if (lane < FEAT) {
                ulonglong2* xw = reinterpret_cast<ulonglong2*>(
                    &sm.xq[bsel ^ 1][lane * XSTR + ob]);
                xw[0] = make_ulonglong2(dup2(xn[0]), dup2(xn[1]));
                xw[1] = make_ulonglong2(dup2(xn[2]), dup2(xn[3]));
            }
        }
        __syncthreads();

        // Head phase per finished chunk: each warp covers its own 2 sample pairs.
        if (slot == CHUNK - 1 && lane < 16) {
            const int tt = lane & 7;
            const int pr = lane >> 3;
            const int gp = 2 * wid + pr;                 // samples (2gp, 2gp+1)
            const ull* hb = &sm.hist[tt][gp][0];
            ull p0 = 0ULL, p1 = 0ULL, pl = 0ULL;
            #pragma unroll
            for (int j = 0; j < HIDDEN; ++j) {
                const ull hv = hb[j];
                p0 = fma2(hv, sm.wcd0[j], p0);
                p1 = fma2(hv, sm.wcd1[j], p1);
                pl = fma2(hv, sm.wcdl[j], pl);
            }
            const float2 q0 = unpack2(p0), q1 = unpack2(p1), ql = unpack2(pl);
            const int tg = t - (CHUNK - 1) + tt;
            const size_t oA = (size_t)(s0 + 2 * gp) * TSTEPS + tg;
            const size_t oB = oA + TSTEPS;
            reinterpret_cast<float2*>(pos_out)[oA] = make_float2(q0.x + cb0, q1.x + cb1);
            reinterpret_cast<float2*>(pos_out)[oB] = make_float2(q0.y + cb0, q1.y + cb1);
            lv_out[oA] = sigf(ql.x + blv);
            lv_out[oB] = sigf(ql.y + blv);
        }
    }

    #pragma unroll
    for (int s = 0; s < 4; ++s) {
        hT_out[(s0 + ob + s) * HIDDEN + lane] = h[s];
        cT_out[(s0 + ob + s) * HIDDEN + lane] = c[s];
    }
}

extern "C" void kernel_launch(void* const* d_in, const int* in_sizes, int n_in,
                              void* d_out, int out_size)
{
    const float* x    = (const float*)d_in[0];
    const float* h0   = (const float*)d_in[1];
    const float* c0   = (const float*)d_in[2];
    const float* W_ih = (const float*)d_in[3];
    const float* W_hh = (const float*)d_in[4];
    const float* b_ih = (const float*)d_in[5];
    const float* b_hh = (const float*)d_in[6];
    const float* W_all= (const float*)d_in[7];
    const float* b_all= (const float*)d_in[8];
    const float* W_pos= (const float*)d_in[9];
    const float* b_pos= (const float*)d_in[10];
    const float* W_lv = (const float*)d_in[11];
    const float* b_lv = (const float*)d_in[12];
    float* out = (float*)d_out;

    lstm_fused_kernel<<<BATCH / NS, 64>>>(x, h0, c0, W_ih, W_hh, b_ih, b_hh,
                                          W_all, b_all, W_pos, b_pos, W_lv, b_lv, out);
}

// round 13
// speedup vs baseline: 1.9761x; 1.0125x over previous
#include <cuda_runtime.h>

#define HIDDEN 32
#define FEAT 30
#define NK 29
#define TSTEPS 512
#define BATCH 4096
#define CHUNK 16
#define TSF (TSTEPS * FEAT)

typedef unsigned long long ull;

// 1 GB scratch: XG[b][t][j] = ((i,f),(g,o)) gate partials (x-part + bias).
__device__ ulonglong2 g_xg[(size_t)BATCH * TSTEPS * HIDDEN];

__device__ __forceinline__ float tanhap(float x) {
    float y; asm("tanh.approx.f32 %0, %1;" : "=f"(y) : "f"(x)); return y;
}
__device__ __forceinline__ float sigf(float x) {
    return fmaf(0.5f, tanhap(0.5f * x), 0.5f);
}
__device__ __forceinline__ ull fma2(ull a, ull b, ull c) {
    ull d;
    asm("fma.rn.f32x2 %0, %1, %2, %3;" : "=l"(d) : "l"(a), "l"(b), "l"(c));
    return d;
}
__device__ __forceinline__ ull pack2(float lo, float hi) {
    ull d; asm("mov.b64 %0, {%1, %2};" : "=l"(d) : "f"(lo), "f"(hi)); return d;
}
__device__ __forceinline__ ull dup2(float v) {
    ull d; asm("mov.b64 %0, {%1, %1};" : "=l"(d) : "f"(v)); return d;
}
__device__ __forceinline__ float2 unpack2(ull v) {
    float lo, hi; asm("mov.b64 {%0, %1}, %2;" : "=f"(lo), "=f"(hi) : "l"(v));
    return make_float2(lo, hi);
}

// ========================== K1: dense x-gates ==============================
// One block per sample b; 8 warps, each covers 64 timesteps in 4 iters of 16.
__global__ void __launch_bounds__(256)
xgate_kernel(const float* __restrict__ x,
             const float* __restrict__ W_ih,
             const float* __restrict__ b_ih, const float* __restrict__ b_hh)
{
    __shared__ ulonglong2 sWih[NK][HIDDEN];   // [k][j] = ((w_i,w_f),(w_g,w_o))
    __shared__ ull xsd[8][NK][16];            // [warp][k][t] dup'd x values

    const int tid  = threadIdx.x;
    const int lane = tid & 31;
    const int wid  = tid >> 5;
    const int b    = blockIdx.x;

    for (int idx = tid; idx < NK * HIDDEN; idx += 256) {
        const int k = idx / HIDDEN, j = idx % HIDDEN;
        sWih[k][j] = make_ulonglong2(
            pack2(W_ih[j * FEAT + k],        W_ih[(32 + j) * FEAT + k]),
            pack2(W_ih[(64 + j) * FEAT + k], W_ih[(96 + j) * FEAT + k]));
    }
    // Bias with mask-bit column (W_ih[:,29] * 1.0) folded in.
    const ull bias_if = pack2(
        b_ih[lane]      + b_hh[lane]      + W_ih[lane * FEAT + 29],
        b_ih[32 + lane] + b_hh[32 + lane] + W_ih[(32 + lane) * FEAT + 29]);
    const ull bias_go = pack2(
        b_ih[64 + lane] + b_hh[64 + lane] + W_ih[(64 + lane) * FEAT + 29],
        b_ih[96 + lane] + b_hh[96 + lane] + W_ih[(96 + lane) * FEAT + 29]);
    __syncthreads();

    const float* xb = x + (size_t)b * TSF;

    #pragma unroll 1
    for (int iter = 0; iter < 4; ++iter) {
        const int t0 = wid * 64 + iter * 16;

        // Stage x[b][t0..t0+15][0..29] dup'd (coalesced reads).
        #pragma unroll
        for (int r = 0; r < 15; ++r) {
            const int idx = r * 32 + lane;         // 0..479
            const int tr = idx / FEAT, k = idx % FEAT;
            const float v = xb[(size_t)t0 * FEAT + idx];
            if (k < NK) xsd[wid][k][tr] = dup2(v);
        }
        __syncwarp();

        ull aif[16], ago[16];
        #pragma unroll
        for (int t = 0; t < 16; ++t) { aif[t] = bias_if; ago[t] = bias_go; }

        #pragma unroll
        for (int k = 0; k < NK; ++k) {
            const ulonglong2 w = sWih[k][lane];
            const ulonglong2* xr = reinterpret_cast<const ulonglong2*>(&xsd[wid][k][0]);
            #pragma unroll
            for (int p = 0; p < 8; ++p) {
                const ulonglong2 xp = xr[p];       // dup'd (x_t, x_t), (x_t+1, x_t+1)
                aif[2 * p]     = fma2(xp.x, w.x, aif[2 * p]);
                ago[2 * p]     = fma2(xp.x, w.y, ago[2 * p]);
                aif[2 * p + 1] = fma2(xp.y, w.x, aif[2 * p + 1]);
                ago[2 * p + 1] = fma2(xp.y, w.y, ago[2 * p + 1]);
            }
        }

        #pragma unroll
        for (int t = 0; t < 16; ++t)
            g_xg[((size_t)b * TSTEPS + t0 + t) * HIDDEN + lane] =
                make_ulonglong2(aif[t], ago[t]);
        __syncwarp();
    }
}

// ========================== K2: recurrence =================================
struct Smem2 {
    ull hq[2][HIDDEN][6];          // [buf][k][s(0..3)+pad] dup'd h; 48B rows
    ulonglong2 hist[CHUNK][33];    // [slot][j] masked-h pairs, padded
    ull wcd0[HIDDEN], wcd1[HIDDEN], wcdl[HIDDEN];
};

__global__ void __launch_bounds__(32)
lstm_rec_kernel(const float* __restrict__ x,
                const float* __restrict__ h0, const float* __restrict__ c0,
                const float* __restrict__ W_hh,
                const float* __restrict__ W_all, const float* __restrict__ b_all,
                const float* __restrict__ W_pos, const float* __restrict__ b_pos,
                const float* __restrict__ W_lv, const float* __restrict__ b_lv,
                float* __restrict__ out)
{
    __shared__ Smem2 sm;
    const int lane = threadIdx.x;
    const int s0 = blockIdx.x * 4;

    ull whh_if[HIDDEN], whh_go[HIDDEN];   // register-resident
    #pragma unroll
    for (int k = 0; k < HIDDEN; ++k) {
        whh_if[k] = pack2(W_hh[lane * HIDDEN + k],        W_hh[(32 + lane) * HIDDEN + k]);
        whh_go[k] = pack2(W_hh[(64 + lane) * HIDDEN + k], W_hh[(96 + lane) * HIDDEN + k]);
    }
    // Folded heads: wc = W_pos @ W_all, cb = W_pos @ b_all + b_pos.
    float wc0 = 0.f, wc1 = 0.f, cb0 = b_pos[0], cb1 = b_pos[1];
    #pragma unroll
    for (int m = 0; m < HIDDEN; ++m) {
        const float wa = W_all[m * HIDDEN + lane];
        wc0 = fmaf(W_pos[m],      wa, wc0);
        wc1 = fmaf(W_pos[32 + m], wa, wc1);
        cb0 = fmaf(W_pos[m],      b_all[m], cb0);
        cb1 = fmaf(W_pos[32 + m], b_all[m], cb1);
    }
    sm.wcd0[lane] = dup2(wc0);
    sm.wcd1[lane] = dup2(wc1);
    sm.wcdl[lane] = dup2(W_lv[lane]);
    const float blv = b_lv[0];

    float h[4], c[4];
    const ulonglong2* xgb[4];
    const float* xmb[4];
    #pragma unroll
    for (int s = 0; s < 4; ++s) {
        h[s] = h0[(s0 + s) * HIDDEN + lane];
        c[s] = c0[(s0 + s) * HIDDEN + lane];
        xgb[s] = &g_xg[(size_t)(s0 + s) * TSTEPS * HIDDEN + lane];
        xmb[s] = x + (size_t)(s0 + s) * TSF + 29;   // mask-bit column
    }
    {
        ulonglong2* hw = reinterpret_cast<ulonglong2*>(&sm.hq[0][lane][0]);
        hw[0] = make_ulonglong2(dup2(h[0]), dup2(h[1]));
        hw[1] = make_ulonglong2(dup2(h[2]), dup2(h[3]));
    }
    // Initial loads for t = 0.
    ulonglong2 xgp[4];
    float mk[4];
    #pragma unroll
    for (int s = 0; s < 4; ++s) { xgp[s] = xgb[s][0]; mk[s] = xmb[s][0]; }
    __syncwarp();

    float* pos_out = out;                                   // [B,T,2]
    float* lv_out  = out + (size_t)BATCH * TSTEPS * 2;      // [B,T,1]
    float* hT_out  = out + (size_t)BATCH * TSTEPS * 3;      // [1,B,H]
    float* cT_out  = hT_out + BATCH * HIDDEN;               // [1,B,H]

    for (int t = 0; t < TSTEPS; ++t) {
        const int bsel = t & 1;
        const int slot = t & (CHUNK - 1);

        // Prefetch next step's gate partials + masks (clamped).
        const int tn = (t + 1 < TSTEPS) ? (t + 1) : t;
        ulonglong2 xgn[4];
        float mn[4];
        #pragma unroll
        for (int s = 0; s < 4; ++s) {
            xgn[s] = xgb[s][(size_t)tn * HIDDEN];
            mn[s]  = xmb[s][(size_t)tn * FEAT];
        }

        // Gates = xg + h @ W_hh (weights in registers).
        ull aif[4], ago[4];
        #pragma unroll
        for (int s = 0; s < 4; ++s) { aif[s] = xgp[s].x; ago[s] = xgp[s].y; }

        #pragma unroll
        for (int k = 0; k < HIDDEN; ++k) {
            const ulonglong2* hr = reinterpret_cast<const ulonglong2*>(&sm.hq[bsel][k][0]);
            const ulonglong2 h01 = hr[0], h23 = hr[1];
            const ull wi = whh_if[k], wg = whh_go[k];
            aif[0] = fma2(h01.x, wi, aif[0]); ago[0] = fma2(h01.x, wg, ago[0]);
            aif[1] = fma2(h01.y, wi, aif[1]); ago[1] = fma2(h01.y, wg, ago[1]);
            aif[2] = fma2(h23.x, wi, aif[2]); ago[2] = fma2(h23.x, wg, ago[2]);
            aif[3] = fma2(h23.y, wi, aif[3]); ago[3] = fma2(h23.y, wg, ago[3]);
        }

        float hs[4];
        #pragma unroll
        for (int s = 0; s < 4; ++s) {
            const bool act = (mk[s] == 1.0f);
            const float2 g1 = unpack2(aif[s]), g2 = unpack2(ago[s]);
            const float cn = fmaf(sigf(g1.y), c[s], sigf(g1.x) * tanhap(g2.x));
            const float hn = sigf(g2.y) * tanhap(cn);
            c[s]  = act ? cn : c[s];
            h[s]  = act ? hn : h[s];
            hs[s] = act ? hn : 0.f;
        }

        {
            ulonglong2* hw = reinterpret_cast<ulonglong2*>(&sm.hq[bsel ^ 1][lane][0]);
            hw[0] = make_ulonglong2(dup2(h[0]), dup2(h[1]));
            hw[1] = make_ulonglong2(dup2(h[2]), dup2(h[3]));
        }
        sm.hist[slot][lane] = make_ulonglong2(pack2(hs[0], hs[1]), pack2(hs[2], hs[3]));
        __syncwarp();

        // Bulk head phase over the finished 16-step chunk.
        if (slot == CHUNK - 1) {
            const int tt = lane & 15;
            const int pr = lane >> 4;
            const ull* hrow = reinterpret_cast<const ull*>(&sm.hist[tt][0]) + pr;
            ull p0 = 0ULL, p1 = 0ULL, pl = 0ULL;
            #pragma unroll
            for (int j = 0; j < HIDDEN; ++j) {
                const ull hv = hrow[j * 2];
                p0 = fma2(hv, sm.wcd0[j], p0);
                p1 = fma2(hv, sm.wcd1[j], p1);
                pl = fma2(hv, sm.wcdl[j], pl);
            }
            const float2 q0 = unpack2(p0), q1 = unpack2(p1), ql = unpack2(pl);
            const int tg = t - (CHUNK - 1) + tt;
            const size_t oA = (size_t)(s0 + 2 * pr) * TSTEPS + tg;
            const size_t oB = oA + TSTEPS;
            reinterpret_cast<float2*>(pos_out)[oA] = make_float2(q0.x + cb0, q1.x + cb1);
            reinterpret_cast<float2*>(pos_out)[oB] = make_float2(q0.y + cb0, q1.y + cb1);
            lv_out[oA] = sigf(ql.x + blv);
            lv_out[oB] = sigf(ql.y + blv);
            __syncwarp();
        }

        #pragma unroll
        for (int s = 0; s < 4; ++s) { xgp[s] = xgn[s]; mk[s] = mn[s]; }
    }

    #pragma unroll
    for (int s = 0; s < 4; ++s) {
        hT_out[(s0 + s) * HIDDEN + lane] = h[s];
        cT_out[(s0 + s) * HIDDEN + lane] = c[s];
    }
}

extern "C" void kernel_launch(void* const* d_in, const int* in_sizes, int n_in,
                              void* d_out, int out_size)
{
    const float* x    = (const float*)d_in[0];
    const float* h0   = (const float*)d_in[1];
    const float* c0   = (const float*)d_in[2];
    const float* W_ih = (const float*)d_in[3];
    const float* W_hh = (const float*)d_in[4];
    const float* b_ih = (const float*)d_in[5];
    const float* b_hh = (const float*)d_in[6];
    const float* W_all= (const float*)d_in[7];
    const float* b_all= (const float*)d_in[8];
    const float* W_pos= (const float*)d_in[9];
    const float* b_pos= (const float*)d_in[10];
    const float* W_lv = (const float*)d_in[11];
    const float* b_lv = (const float*)d_in[12];
    float* out = (float*)d_out;

    xgate_kernel<<<BATCH, 256>>>(x, W_ih, b_ih, b_hh);
    lstm_rec_kernel<<<BATCH / 4, 32>>>(x, h0, c0, W_hh,
                                       W_all, b_all, W_pos, b_pos, W_lv, b_lv, out);
}